// round 1
// baseline (speedup 1.0000x reference)
#include <cuda_runtime.h>

#define N_SAMPLES 65536
#define TPB 1024
#define EPT 64            // elements per thread: 1024*64 = 65536
#define SR_D 44100.0

__global__ __launch_bounds__(TPB, 1)
void amfm_kernel(const float* __restrict__ theta_am,
                 const float* __restrict__ theta_fm,
                 const float* __restrict__ phase,
                 const float* __restrict__ phase_am,
                 const float* __restrict__ phase_fm,
                 const float* __restrict__ u_am_mi,
                 const float* __restrict__ u_fm_hz,
                 const float* __restrict__ u_f0_hz,
                 float* __restrict__ out)
{
    const int b   = blockIdx.x;
    const int tid = threadIdx.x;
    const float  TWOPI_F  = 6.28318530717958647692f;   // fl32(2*pi) = 0x40C90FDB
    const double TWOPI_FD = (double)TWOPI_F;

    __shared__ double s_base_d, s_fmt_d, s_amt_d, s_p0_d, s_pfm_d, s_pam_d;
    __shared__ float  s_mfm, s_miam, s_fmt, s_amt, s_bh, s_bl;
    __shared__ double s_warp[32];

    if (tid == 0) {
        // range constants exactly as reference computes them (double log2, then fp32)
        const double lg_hi  = log2(8.0);
        const double lg_lo  = log2(0.5);
        const double lg_f0l = log2(32.7);
        const double lg_f0h = log2(523.25);
        const float d_amfm  = (float)(lg_hi - lg_lo);   // 4.0f
        const float lo_amfm = (float)lg_lo;             // -1.0f
        const float d_f0    = (float)(lg_f0h - lg_f0l);
        const float lo_f0   = (float)lg_f0l;

        // replicate reference fp32 op chain: u*(hi-lo) + lo (separate mul, add)
        float xa = __fadd_rn(__fmul_rn(theta_am[b], d_amfm), lo_amfm);
        float xf = __fadd_rn(__fmul_rn(u_fm_hz[b], d_amfm), lo_amfm);
        float x0 = __fadd_rn(__fmul_rn(u_f0_hz[b], d_f0),   lo_f0);
        // correctly-rounded fp32 exp2 via double
        float am_hz = (float)exp2((double)xa);
        float fm_hz = (float)exp2((double)xf);
        float f0_hz = (float)exp2((double)x0);

        // coherent frequency words exactly as reference rounds them
        float w0  = __fmul_rn(TWOPI_F, f0_hz);
        float wfm = __fmul_rn(TWOPI_F, fm_hz);
        float wam = __fmul_rn(TWOPI_F, am_hz);

        const double denom = SR_D * TWOPI_FD;
        double base_d = (double)w0 / denom;            // carrier turns/sample
        s_base_d = base_d;
        s_fmt_d  = (double)wfm / denom;
        s_amt_d  = (double)wam / denom;
        s_p0_d   = (double)__fmul_rn(TWOPI_F, phase[b])    / TWOPI_FD;
        s_pfm_d  = (double)__fmul_rn(TWOPI_F, phase_fm[b]) / TWOPI_FD;
        s_pam_d  = (double)__fmul_rn(TWOPI_F, phase_am[b]) / TWOPI_FD;
        s_mfm  = (float)(((double)w0 * (double)theta_fm[b]) / denom); // fm depth, turns/sample
        s_miam = u_am_mi[b];
        s_fmt  = (float)((double)wfm / denom);
        s_amt  = (float)((double)wam / denom);
        float bh = (float)base_d;
        s_bh = bh;
        s_bl = (float)(base_d - (double)bh);           // low word of base slope
    }
    __syncthreads();

    const float  mfm = s_mfm, miam = s_miam, fmt = s_fmt, amt = s_amt;
    const float  bh = s_bh, bl = s_bl;
    const double base_d = s_base_d, fmt_d = s_fmt_d, amt_d = s_amt_d;
    const double p0_d = s_p0_d, pfm_d = s_pfm_d, pam_d = s_pam_d;

    const int a = tid * EPT;

    // per-thread start fractions for fm/am phases (exact in double, frac'd)
    double fm_start = fmt_d * (double)a + pfm_d;
    const float ft0 = (float)(fm_start - floor(fm_start));
    double am_start = amt_d * (double)a + pam_d;
    const float at0 = (float)(am_start - floor(am_start));

    // ---------- pass 1: Kahan sum of modulated increment part (bl + mfm*sin) ----------
    float ms = 0.0f, mc = 0.0f;
    {
        float kf = 0.0f;
        #pragma unroll 8
        for (int k = 0; k < EPT; k++) {
            float ft = fmaf(fmt, kf, ft0);
            float rf = ft - rintf(ft);                 // [-0.5, 0.5] turns
            float sf = __sinf(TWOPI_F * rf);           // |arg| <= pi
            float v  = fmaf(mfm, sf, bl);
            float y = v - mc; float t = ms + y; mc = (t - ms) - y; ms = t;
            kf += 1.0f;
        }
    }
    double my_mod = (double)ms - (double)mc;

    // ---------- block-wide exclusive scan of per-thread mod sums (double) ----------
    const unsigned FULL = 0xffffffffu;
    const int lane = tid & 31;
    const int wrp  = tid >> 5;
    double v = my_mod;
    #pragma unroll
    for (int o = 1; o < 32; o <<= 1) {
        double n = __shfl_up_sync(FULL, v, o);
        if (lane >= o) v += n;
    }
    if (lane == 31) s_warp[wrp] = v;
    __syncthreads();
    if (wrp == 0) {
        double wv = s_warp[lane];
        #pragma unroll
        for (int o = 1; o < 32; o <<= 1) {
            double n = __shfl_up_sync(FULL, wv, o);
            if (lane >= o) wv += n;
        }
        s_warp[lane] = wv;
    }
    __syncthreads();
    double excl = (v - my_mod) + (wrp > 0 ? s_warp[wrp - 1] : 0.0);

    // ---------- starting carrier phase for this thread (turns, frac'd) ----------
    double off = p0_d + base_d * (double)a + excl;
    off -= floor(off);
    float s = (float)off;
    float c = -(float)(off - (double)s);               // Kahan: truth ~= s - c

    // ---------- pass 2: synthesize + write (float4 stores) ----------
    float4* __restrict__ o4 = (float4*)(out + (size_t)b * N_SAMPLES + a);
    float kf = 0.0f;
    #pragma unroll 4
    for (int k4 = 0; k4 < EPT / 4; k4++) {
        float tmp[4];
        #pragma unroll
        for (int j = 0; j < 4; j++) {
            // fm modulator
            float ft = fmaf(fmt, kf, ft0);
            float rf = ft - rintf(ft);
            float sf = __sinf(TWOPI_F * rf);
            // carrier increment (turns): bh + (bl + mfm*sf)
            float vv = __fadd_rn(bh, fmaf(mfm, sf, bl));
            // Kahan accumulate + exact wrap at 1 turn
            float y = vv - c; float t = s + y; c = (t - s) - y; s = t;
            if (s >= 1.0f) s -= 1.0f;
            // carrier sine
            float rc = s - c;
            float u  = rc - rintf(rc);
            float xc = __sinf(TWOPI_F * u);
            // am modulator
            float at = fmaf(amt, kf, at0);
            float ra = at - rintf(at);
            float sa = __sinf(TWOPI_F * ra);
            tmp[j] = 0.5f * xc * fmaf(miam, sa, 1.0f);
            kf += 1.0f;
        }
        float4 o; o.x = tmp[0]; o.y = tmp[1]; o.z = tmp[2]; o.w = tmp[3];
        o4[k4] = o;
    }
}

extern "C" void kernel_launch(void* const* d_in, const int* in_sizes, int n_in,
                              void* d_out, int out_size) {
    const int B = in_sizes[0];   // 256 rows
    amfm_kernel<<<B, TPB>>>(
        (const float*)d_in[0],   // theta_am_0to1
        (const float*)d_in[1],   // theta_fm_0to1
        (const float*)d_in[2],   // phase
        (const float*)d_in[3],   // phase_am
        (const float*)d_in[4],   // phase_fm
        (const float*)d_in[5],   // u_am_mi
        (const float*)d_in[6],   // u_fm_hz
        (const float*)d_in[7],   // u_f0_hz
        (float*)d_out);
}

// round 2
// speedup vs baseline: 1.0988x; 1.0988x over previous
#include <cuda_runtime.h>

#define N_SAMPLES 65536
#define TPB 256
#define EPT 32
#define CHUNKS (N_SAMPLES / (TPB * EPT))   // 8
#define MAXB 1024
#define SR_D 44100.0

struct RowP {
    double base_rad;   // carrier rad/sample  = (double)fl32(2pi*f0) / SR
    double fm_rad;     // fm modulator rad/sample
    double am_rad;
    double mfm_rad;    // fm depth, rad/sample (double)
    double p0_rad, pfm_rad, pam_rad;
    double K1, K2, c2; // S(n) = K1 - K2*cos(n*fm_rad + c2)
    float base_f, mfm_f, fmt_f, amt_f, miam_f;
};

__device__ RowP g_rows[MAXB];

__global__ void setup_kernel(const float* __restrict__ theta_am,
                             const float* __restrict__ theta_fm,
                             const float* __restrict__ phase,
                             const float* __restrict__ phase_am,
                             const float* __restrict__ phase_fm,
                             const float* __restrict__ u_am_mi,
                             const float* __restrict__ u_fm_hz,
                             const float* __restrict__ u_f0_hz,
                             int B)
{
    int b = blockIdx.x * blockDim.x + threadIdx.x;
    if (b >= B) return;
    const float TWOPI_F = 6.28318530717958647692f;   // fl32(2*pi)

    // range constants exactly as reference (double log2, rounded to fp32)
    const double lg_lo  = -1.0;                       // log2(0.5)
    const double lg_d   = 4.0;                        // log2(8)-log2(0.5)
    const double lgf0l  = log2(32.7);
    const double lgf0h  = log2(523.25);

    // replicate reference fp32 op chain: u*(hi-lo) + lo
    float xa = __fadd_rn(__fmul_rn(theta_am[b], (float)lg_d), (float)lg_lo);
    float xf = __fadd_rn(__fmul_rn(u_fm_hz[b], (float)lg_d), (float)lg_lo);
    float x0 = __fadd_rn(__fmul_rn(u_f0_hz[b], (float)(lgf0h - lgf0l)), (float)lgf0l);
    float am_hz = (float)exp2((double)xa);
    float fm_hz = (float)exp2((double)xf);
    float f0_hz = (float)exp2((double)x0);

    // coherent frequency words, rounded exactly as reference rounds them
    double w0  = (double)__fmul_rn(TWOPI_F, f0_hz);
    double wfm = (double)__fmul_rn(TWOPI_F, fm_hz);
    double wam = (double)__fmul_rn(TWOPI_F, am_hz);

    RowP r;
    r.base_rad = w0  / SR_D;
    r.fm_rad   = wfm / SR_D;
    r.am_rad   = wam / SR_D;
    r.mfm_rad  = w0 * (double)theta_fm[b] / SR_D;
    r.p0_rad   = (double)__fmul_rn(TWOPI_F, phase[b]);
    r.pfm_rad  = (double)__fmul_rn(TWOPI_F, phase_fm[b]);
    r.pam_rad  = (double)__fmul_rn(TWOPI_F, phase_am[b]);

    // closed form for the exclusive prefix sum of the FM modulator sine:
    //   S(n) = sum_{i=0}^{n-1} sin(pfm + i*fm_rad)
    //        = [cos(pfm - d/2) - cos(n*d + (pfm - d/2))] / (2 sin(d/2))
    double half = 0.5 * r.fm_rad;
    r.K2 = 0.5 / sin(half);
    r.c2 = r.pfm_rad - half;
    r.K1 = r.K2 * cos(r.c2);

    r.base_f = (float)r.base_rad;
    r.mfm_f  = (float)r.mfm_rad;
    r.fmt_f  = (float)r.fm_rad;
    r.amt_f  = (float)r.am_rad;
    r.miam_f = u_am_mi[b];
    g_rows[b] = r;
}

// reduce double angle to float in ~[-pi, pi]
__device__ __forceinline__ float red2pi(double x) {
    const double TWO_PI_D = 6.283185307179586476925286766559;
    const double INV2PI_D = 0.15915494309189533576888376337251;
    double q = rint(x * INV2PI_D);
    return (float)(x - q * TWO_PI_D);
}

__global__ __launch_bounds__(TPB, 7)
void amfm_main(float* __restrict__ out)
{
    const int row   = blockIdx.x >> 3;       // / CHUNKS
    const int chunk = blockIdx.x & (CHUNKS - 1);
    const RowP* __restrict__ rp = &g_rows[row];

    const int    a = (chunk * TPB + (int)threadIdx.x) * EPT;
    const double n = (double)a;

    const double fm_rad = rp->fm_rad;
    // exclusive modulation prefix (exact analytic sum, double)
    double S   = rp->K1 - rp->K2 * cos(fma(n, fm_rad, rp->c2));
    double off = rp->p0_rad + rp->base_rad * n + rp->mfm_rad * S;

    float s  = red2pi(off);                                  // carrier phase (rad)
    float ft = red2pi(fma(n, fm_rad,      rp->pfm_rad));     // fm phase
    float at = red2pi(fma(n, rp->am_rad,  rp->pam_rad));     // am phase

    const float basef = rp->base_f, mfmf = rp->mfm_f, fmtf = rp->fmt_f,
                amtf  = rp->amt_f,  miamf = rp->miam_f;
    const float PI_F    = 3.14159265358979323846f;
    const float TWOPI_F = 6.28318530717958647692f;

    float4* __restrict__ o4 = (float4*)(out + (size_t)row * N_SAMPLES + a);

    #pragma unroll
    for (int k4 = 0; k4 < EPT / 4; k4++) {
        float v[4];
        #pragma unroll
        for (int j = 0; j < 4; j++) {
            float sf = __sinf(ft);                       // fm modulator
            s += fmaf(mfmf, sf, basef);                  // phase increment (rad)
            s -= (s > PI_F) ? TWOPI_F : 0.0f;            // wrap (<=1 per thread-pass)
            float xc = __sinf(s);                        // carrier
            float sa = __sinf(at);                       // am modulator
            v[j] = (0.5f * xc) * fmaf(miamf, sa, 1.0f);
            ft += fmtf;
            at += amtf;
        }
        float4 o; o.x = v[0]; o.y = v[1]; o.z = v[2]; o.w = v[3];
        o4[k4] = o;
    }
}

extern "C" void kernel_launch(void* const* d_in, const int* in_sizes, int n_in,
                              void* d_out, int out_size) {
    const int B = in_sizes[0];   // 256 rows
    setup_kernel<<<(B + 255) / 256, 256>>>(
        (const float*)d_in[0],   // theta_am_0to1
        (const float*)d_in[1],   // theta_fm_0to1
        (const float*)d_in[2],   // phase
        (const float*)d_in[3],   // phase_am
        (const float*)d_in[4],   // phase_fm
        (const float*)d_in[5],   // u_am_mi
        (const float*)d_in[6],   // u_fm_hz
        (const float*)d_in[7],   // u_f0_hz
        B);
    amfm_main<<<B * CHUNKS, TPB>>>((float*)d_out);
}